// round 5
// baseline (speedup 1.0000x reference)
#include <cuda_runtime.h>
#include <cstdint>

// AR(24) rollout: out[b, t, d], t in [0,168), seeded from x[b, 312..335, d].
// One thread = two adjacent d channels via packed fma.rn.f32x2 (FFMA2).
// R4/R5 change: 3-way accumulator split per step to break the serial FMA chain
// (96-cycle dependent chain -> ~40 cycles, ILP=3), so ~3.5 warps/SMSP can
// saturate the 0.5 FFMA2/cyc fma pipe.
//
// Shapes: x [256,336,512] f32, W [24,1] f32, b [1] f32, out [256,168,512] f32

#define ORDER 24
#define T_OUT 168
#define D_DIM 512
#define B_DIM 256
#define S_DIM 336
#define HALF_D (D_DIM / 2)

__global__ __launch_bounds__(256, 2)
void ar_ffma2_kernel(const float* __restrict__ x,
                     const float* __restrict__ W,
                     const float* __restrict__ bias,
                     float* __restrict__ out) {
    const int p = blockIdx.x * blockDim.x + threadIdx.x;  // pair index
    const int b = p / HALF_D;
    const int d = (p - b * HALF_D) * 2;

    // duplicated-pair coefficients (lo == hi == W[k])
    unsigned long long wk[ORDER];
#pragma unroll
    for (int k = 0; k < ORDER; k++) {
        unsigned int wi = __float_as_uint(__ldg(&W[k]));
        wk[k] = ((unsigned long long)wi << 32) | (unsigned long long)wi;
    }
    unsigned long long bias2;
    {
        unsigned int bi = __float_as_uint(__ldg(bias));
        bias2 = ((unsigned long long)bi << 32) | (unsigned long long)bi;
    }

    // seed window: last ORDER timesteps (coalesced 8B loads)
    unsigned long long win[ORDER];
    const float* xp = x + (size_t)b * S_DIM * D_DIM + (size_t)(S_DIM - ORDER) * D_DIM + d;
#pragma unroll
    for (int k = 0; k < ORDER; k++) {
        win[k] = *reinterpret_cast<const unsigned long long*>(xp + (size_t)k * D_DIM);
    }

    float* op = out + (size_t)b * T_OUT * D_DIM + d;

    // 168 = 7 * 24; inner 24 steps fully unrolled -> (i+k)%24 is compile-time.
#pragma unroll 1
    for (int outer = 0; outer < T_OUT / ORDER; outer++) {
#pragma unroll
        for (int i = 0; i < ORDER; i++) {
            // three independent chains: k in [0,8), [8,16), [16,24).
            // win[i] (written by previous step) is consumed only at k=23,
            // the tail of chain 2 -> steps pipeline cleanly.
            unsigned long long a0 = bias2, a1, a2;
            asm("mul.rn.f32x2 %0, %1, %2;" : "=l"(a1)
                : "l"(wk[8]),  "l"(win[(i + 8) % ORDER]));
            asm("mul.rn.f32x2 %0, %1, %2;" : "=l"(a2)
                : "l"(wk[16]), "l"(win[(i + 16) % ORDER]));
#pragma unroll
            for (int k = 0; k < 8; k++) {
                asm("fma.rn.f32x2 %0, %1, %2, %0;" : "+l"(a0)
                    : "l"(wk[k]), "l"(win[(i + k) % ORDER]));
            }
#pragma unroll
            for (int k = 9; k < 16; k++) {
                asm("fma.rn.f32x2 %0, %1, %2, %0;" : "+l"(a1)
                    : "l"(wk[k]), "l"(win[(i + k) % ORDER]));
            }
#pragma unroll
            for (int k = 17; k < 24; k++) {
                asm("fma.rn.f32x2 %0, %1, %2, %0;" : "+l"(a2)
                    : "l"(wk[k]), "l"(win[(i + k) % ORDER]));
            }
            unsigned long long acc;
            asm("add.rn.f32x2 %0, %1, %2;" : "=l"(acc) : "l"(a0), "l"(a1));
            asm("add.rn.f32x2 %0, %1, %0;" : "+l"(acc) : "l"(a2));

            win[i] = acc;
            *reinterpret_cast<unsigned long long*>(
                op + (size_t)(outer * ORDER + i) * D_DIM) = acc;
        }
    }
}

extern "C" void kernel_launch(void* const* d_in, const int* in_sizes, int n_in,
                              void* d_out, int out_size) {
    const float* x  = (const float*)d_in[0];   // [256, 336, 512]
    const float* W  = (const float*)d_in[1];   // [24, 1]
    const float* bs = (const float*)d_in[2];   // [1]
    float* out = (float*)d_out;                // [256, 168, 512]

    const int n_threads = B_DIM * HALF_D;      // 65536
    const int block = 256;
    ar_ffma2_kernel<<<n_threads / block, block>>>(x, W, bs, out);
}

// round 6
// speedup vs baseline: 1.4804x; 1.4804x over previous
#include <cuda_runtime.h>
#include <cstdint>

// AR(24) rollout: out[b, t, d], t in [0,168), seeded from x[b, 312..335, d].
// One thread = two adjacent d channels via packed fma.rn.f32x2 (FFMA2).
// R6: 2-way accumulator split (R5's 3-way split pushed regs past ptxas's
// spill heuristic under launch_bounds(256,2) -> wk[] spilled to local,
// 80 regs + 2x slowdown). 2-way costs only +3 regs: ~114 < 128 cap.
//
// Shapes: x [256,336,512] f32, W [24,1] f32, b [1] f32, out [256,168,512] f32

#define ORDER 24
#define T_OUT 168
#define D_DIM 512
#define B_DIM 256
#define S_DIM 336
#define HALF_D (D_DIM / 2)

__global__ __launch_bounds__(256, 2)
void ar_ffma2_kernel(const float* __restrict__ x,
                     const float* __restrict__ W,
                     const float* __restrict__ bias,
                     float* __restrict__ out) {
    const int p = blockIdx.x * blockDim.x + threadIdx.x;  // pair index
    const int b = p / HALF_D;
    const int d = (p - b * HALF_D) * 2;

    // duplicated-pair coefficients (lo == hi == W[k])
    unsigned long long wk[ORDER];
#pragma unroll
    for (int k = 0; k < ORDER; k++) {
        unsigned int wi = __float_as_uint(__ldg(&W[k]));
        wk[k] = ((unsigned long long)wi << 32) | (unsigned long long)wi;
    }
    unsigned long long bias2;
    {
        unsigned int bi = __float_as_uint(__ldg(bias));
        bias2 = ((unsigned long long)bi << 32) | (unsigned long long)bi;
    }

    // seed window: last ORDER timesteps (coalesced 8B loads)
    unsigned long long win[ORDER];
    const float* xp = x + (size_t)b * S_DIM * D_DIM + (size_t)(S_DIM - ORDER) * D_DIM + d;
#pragma unroll
    for (int k = 0; k < ORDER; k++) {
        win[k] = *reinterpret_cast<const unsigned long long*>(xp + (size_t)k * D_DIM);
    }

    float* op = out + (size_t)b * T_OUT * D_DIM + d;

    // 168 = 7 * 24; inner 24 steps fully unrolled -> (i+k)%24 is compile-time.
#pragma unroll 1
    for (int outer = 0; outer < T_OUT / ORDER; outer++) {
#pragma unroll
        for (int i = 0; i < ORDER; i++) {
            // two independent chains: k in [0,12) and [12,24).
            // win[i] (written by the previous step) is consumed only at k=23,
            // the tail of chain 1 -> the cross-step serial path stays 1 FMA.
            unsigned long long a0 = bias2, a1;
            asm("mul.rn.f32x2 %0, %1, %2;" : "=l"(a1)
                : "l"(wk[12]), "l"(win[(i + 12) % ORDER]));
#pragma unroll
            for (int k = 0; k < 12; k++) {
                asm("fma.rn.f32x2 %0, %1, %2, %0;" : "+l"(a0)
                    : "l"(wk[k]), "l"(win[(i + k) % ORDER]));
            }
#pragma unroll
            for (int k = 13; k < 24; k++) {
                asm("fma.rn.f32x2 %0, %1, %2, %0;" : "+l"(a1)
                    : "l"(wk[k]), "l"(win[(i + k) % ORDER]));
            }
            unsigned long long acc;
            asm("add.rn.f32x2 %0, %1, %2;" : "=l"(acc) : "l"(a0), "l"(a1));

            win[i] = acc;
            *reinterpret_cast<unsigned long long*>(
                op + (size_t)(outer * ORDER + i) * D_DIM) = acc;
        }
    }
}

extern "C" void kernel_launch(void* const* d_in, const int* in_sizes, int n_in,
                              void* d_out, int out_size) {
    const float* x  = (const float*)d_in[0];   // [256, 336, 512]
    const float* W  = (const float*)d_in[1];   // [24, 1]
    const float* bs = (const float*)d_in[2];   // [1]
    float* out = (float*)d_out;                // [256, 168, 512]

    const int n_threads = B_DIM * HALF_D;      // 65536
    const int block = 256;
    ar_ffma2_kernel<<<n_threads / block, block>>>(x, W, bs, out);
}

// round 7
// speedup vs baseline: 1.6045x; 1.0838x over previous
#include <cuda_runtime.h>
#include <cstdint>

// AR(24) rollout: out[b, t, d], t in [0,168), seeded from x[b, 312..335, d].
// One thread = two adjacent d channels via packed fma.rn.f32x2 (FFMA2).
// R7: weights moved to SMEM (dup-packed, broadcast LDS.128 = 2 coeffs/load).
// R5/R6 showed the 48-reg wk[] array + 48-reg window + 64-bit pair
// fragmentation trips ptxas's spill heuristic at the 128-reg cap; staging wk
// in shared memory frees ~48 regs so the window + pipelined accumulators fit.
//
// Shapes: x [256,336,512] f32, W [24,1] f32, b [1] f32, out [256,168,512] f32

#define ORDER 24
#define T_OUT 168
#define D_DIM 512
#define B_DIM 256
#define S_DIM 336
#define HALF_D (D_DIM / 2)
#define BLOCK 128

__global__ __launch_bounds__(BLOCK, 4)
void ar_ffma2_kernel(const float* __restrict__ x,
                     const float* __restrict__ W,
                     const float* __restrict__ bias,
                     float* __restrict__ out) {
    // dup-packed weights in shared memory: ws[k] = (W[k], W[k]) as b64.
    __shared__ __align__(16) unsigned long long ws[ORDER + 2];

    const int tid = threadIdx.x;
    if (tid < ORDER) {
        unsigned int wi = __float_as_uint(W[tid]);
        ws[tid] = ((unsigned long long)wi << 32) | (unsigned long long)wi;
    }

    unsigned long long bias2;
    {
        unsigned int bi = __float_as_uint(__ldg(bias));
        bias2 = ((unsigned long long)bi << 32) | (unsigned long long)bi;
    }

    const int p = blockIdx.x * BLOCK + tid;   // pair index in [0, B*HALF_D)
    const int b = p / HALF_D;
    const int d = (p - b * HALF_D) * 2;

    // seed window: last ORDER timesteps (coalesced 8B loads)
    unsigned long long win[ORDER];
    const float* xp = x + (size_t)b * S_DIM * D_DIM + (size_t)(S_DIM - ORDER) * D_DIM + d;
#pragma unroll
    for (int k = 0; k < ORDER; k++) {
        win[k] = *reinterpret_cast<const unsigned long long*>(xp + (size_t)k * D_DIM);
    }

    __syncthreads();

    // 32-bit shared address of ws for ld.shared
    unsigned int ws_addr;
    asm("{ .reg .u64 t; cvta.to.shared.u64 t, %1; cvt.u32.u64 %0, t; }"
        : "=r"(ws_addr) : "l"(ws));

    float* op = out + (size_t)b * T_OUT * D_DIM + d;

    // 168 = 7 * 24; inner 24 steps fully unrolled -> (i+k)%24 is compile-time.
#pragma unroll 1
    for (int outer = 0; outer < T_OUT / ORDER; outer++) {
#pragma unroll
        for (int i = 0; i < ORDER; i++) {
            unsigned long long acc = bias2;
            // 12 x (LDS.128 -> 2 dup-packed coeffs -> 2 FFMA2).
            // volatile: prevent CSE across steps (would hoist 24 coeffs into
            // registers and recreate the R5/R6 spill).
#pragma unroll
            for (int j = 0; j < ORDER / 2; j++) {
                unsigned long long c0, c1;
                asm volatile("ld.shared.v2.b64 {%0, %1}, [%2];"
                             : "=l"(c0), "=l"(c1)
                             : "r"(ws_addr + 16u * j));
                asm("fma.rn.f32x2 %0, %1, %2, %0;" : "+l"(acc)
                    : "l"(c0), "l"(win[(i + 2 * j) % ORDER]));
                asm("fma.rn.f32x2 %0, %1, %2, %0;" : "+l"(acc)
                    : "l"(c1), "l"(win[(i + 2 * j + 1) % ORDER]));
            }
            win[i] = acc;   // new value replaces the oldest slot
            *reinterpret_cast<unsigned long long*>(
                op + (size_t)(outer * ORDER + i) * D_DIM) = acc;
        }
    }
}

extern "C" void kernel_launch(void* const* d_in, const int* in_sizes, int n_in,
                              void* d_out, int out_size) {
    const float* x  = (const float*)d_in[0];   // [256, 336, 512]
    const float* W  = (const float*)d_in[1];   // [24, 1]
    const float* bs = (const float*)d_in[2];   // [1]
    float* out = (float*)d_out;                // [256, 168, 512]

    const int n_threads = B_DIM * HALF_D;      // 65536
    ar_ffma2_kernel<<<n_threads / BLOCK, BLOCK>>>(x, W, bs, out);
}